// round 1
// baseline (speedup 1.0000x reference)
#include <cuda_runtime.h>
#include <cuda_fp16.h>
#include <cstdint>
#include <math.h>

// Problem constants
#define NB   16
#define SEQ  2048
#define DM   768   // D_TO = D_FROM = H = 768

// ---------------- scratch (device globals; no runtime allocation) ----------
__device__ __half g_Q[(long long)NB * SEQ * DM];   // fp16 Q (pre-scaled by 1/sqrt(H))
__device__ __half g_K[(long long)NB * SEQ * DM];
__device__ __half g_V[(long long)NB * SEQ * DM];
__device__ float  g_S[(long long)NB * SEQ * SEQ];  // fp32 scores
__device__ __half g_P[(long long)NB * SEQ * SEQ];  // fp16 softmax probs

// ---------------- PTX helpers ----------------------------------------------
__device__ __forceinline__ uint32_t smem_u32(const void* p) {
    return (uint32_t)__cvta_generic_to_shared(p);
}
__device__ __forceinline__ void ldm_x4(uint32_t* d, uint32_t a) {
    asm volatile("ldmatrix.sync.aligned.m8n8.x4.shared.b16 {%0,%1,%2,%3}, [%4];"
                 : "=r"(d[0]), "=r"(d[1]), "=r"(d[2]), "=r"(d[3]) : "r"(a));
}
__device__ __forceinline__ void ldm_x2(uint32_t* d, uint32_t a) {
    asm volatile("ldmatrix.sync.aligned.m8n8.x2.shared.b16 {%0,%1}, [%2];"
                 : "=r"(d[0]), "=r"(d[1]) : "r"(a));
}
__device__ __forceinline__ void ldm_x2t(uint32_t* d, uint32_t a) {
    asm volatile("ldmatrix.sync.aligned.m8n8.x2.trans.shared.b16 {%0,%1}, [%2];"
                 : "=r"(d[0]), "=r"(d[1]) : "r"(a));
}
__device__ __forceinline__ void mma16816(float* c, const uint32_t* a, const uint32_t* b) {
    asm volatile("mma.sync.aligned.m16n8k16.row.col.f32.f16.f16.f32 "
                 "{%0,%1,%2,%3}, {%4,%5,%6,%7}, {%8,%9}, {%0,%1,%2,%3};"
                 : "+f"(c[0]), "+f"(c[1]), "+f"(c[2]), "+f"(c[3])
                 : "r"(a[0]), "r"(a[1]), "r"(a[2]), "r"(a[3]),
                   "r"(b[0]), "r"(b[1]));
}

// ---------------- generic tiled MMA GEMM ------------------------------------
// C[M,N] = A[M,K] * op(B) (+bias)(*scale), fp32 accumulate.
// CONVERT: A,B sources are fp32 (converted to fp16 while staging). Else fp16.
// TRANS_B: B source is row-major [N,K] (i.e. math does A*B^T). Else [K,N].
// OUT_HALF: write fp16 (with bias+scale), else fp32.
// Tiles: BM=BN=128, BK=32; 256 threads; 8 warps in 2x4, each warp 64x32.
// All dims assumed divisible by tiles (true for this problem).
template <bool CONVERT, bool TRANS_B, bool OUT_HALF, bool HAS_BIAS>
__global__ void __launch_bounds__(256)
gemm_k(const void* __restrict__ Ag_, const void* __restrict__ Bg_,
       const float* __restrict__ bias, void* __restrict__ Cg_,
       int Kd, int lda, int ldb, int ldc, float scale,
       long long strA, long long strB, long long strC)
{
    constexpr int BM = 128, BN = 128, BK = 32;
    constexpr int ASTR   = BK + 8;   // 40 halves
    constexpr int BSTR_T = BK + 8;   // 40 halves ([BN][BK])
    constexpr int BSTR_N = BN + 8;   // 136 halves ([BK][BN])

    __shared__ __half AsRaw[BM * ASTR];
    __shared__ __half BsRaw[TRANS_B ? (BN * BSTR_T) : (BK * BSTR_N)];

    const int z    = blockIdx.z;
    const int row0 = blockIdx.y * BM;
    const int col0 = blockIdx.x * BN;
    const int tid  = threadIdx.x;
    const int lane = tid & 31;
    const int warp = tid >> 5;
    const int wr   = warp >> 2;   // 0..1
    const int wc   = warp & 3;    // 0..3

    float acc[4][4][4];
#pragma unroll
    for (int i = 0; i < 4; ++i)
#pragma unroll
        for (int j = 0; j < 4; ++j)
#pragma unroll
            for (int r = 0; r < 4; ++r) acc[i][j][r] = 0.f;

    for (int kt = 0; kt < Kd; kt += BK) {
        // ---- stage A tile [BM][BK] ----
        if constexpr (CONVERT) {
            const float* A = (const float*)Ag_ + (size_t)z * strA;
#pragma unroll
            for (int it = 0; it < 4; ++it) {
                int f4 = tid + it * 256;
                int r = f4 >> 3, c4 = (f4 & 7) << 2;
                float4 v = *(const float4*)(A + (size_t)(row0 + r) * lda + kt + c4);
                __half2* dst = (__half2*)&AsRaw[r * ASTR + c4];
                dst[0] = __floats2half2_rn(v.x, v.y);
                dst[1] = __floats2half2_rn(v.z, v.w);
            }
        } else {
            const __half* A = (const __half*)Ag_ + (size_t)z * strA;
#pragma unroll
            for (int it = 0; it < 2; ++it) {
                int f4 = tid + it * 256;
                int r = f4 >> 2, c8 = (f4 & 3) << 3;
                *(float4*)&AsRaw[r * ASTR + c8] =
                    *(const float4*)(A + (size_t)(row0 + r) * lda + kt + c8);
            }
        }
        // ---- stage B tile ----
        if constexpr (TRANS_B) {
            // source row-major [N,K]: tile [BN][BK]
            const __half* Bp = (const __half*)Bg_ + (size_t)z * strB;
#pragma unroll
            for (int it = 0; it < 2; ++it) {
                int f4 = tid + it * 256;
                int r = f4 >> 2, c8 = (f4 & 3) << 3;
                *(float4*)&BsRaw[r * BSTR_T + c8] =
                    *(const float4*)(Bp + (size_t)(col0 + r) * ldb + kt + c8);
            }
        } else {
            if constexpr (CONVERT) {
                const float* Bp = (const float*)Bg_ + (size_t)z * strB;
#pragma unroll
                for (int it = 0; it < 4; ++it) {
                    int f4 = tid + it * 256;
                    int r = f4 >> 5, c4 = (f4 & 31) << 2;
                    float4 v = *(const float4*)(Bp + (size_t)(kt + r) * ldb + col0 + c4);
                    __half2* dst = (__half2*)&BsRaw[r * BSTR_N + c4];
                    dst[0] = __floats2half2_rn(v.x, v.y);
                    dst[1] = __floats2half2_rn(v.z, v.w);
                }
            } else {
                const __half* Bp = (const __half*)Bg_ + (size_t)z * strB;
#pragma unroll
                for (int it = 0; it < 2; ++it) {
                    int f4 = tid + it * 256;
                    int r = f4 >> 4, c8 = (f4 & 15) << 3;
                    *(float4*)&BsRaw[r * BSTR_N + c8] =
                        *(const float4*)(Bp + (size_t)(kt + r) * ldb + col0 + c8);
                }
            }
        }
        __syncthreads();

#pragma unroll
        for (int ks = 0; ks < 2; ++ks) {
            const int k16 = ks * 16;
            uint32_t a[4][4], b[4][2];
            const int arow = (lane & 15);
            const int acol = k16 + ((lane >> 4) << 3);
#pragma unroll
            for (int i = 0; i < 4; ++i)
                ldm_x4(a[i], smem_u32(&AsRaw[(wr * 64 + i * 16 + arow) * ASTR + acol]));

            if constexpr (TRANS_B) {
                const int l = lane & 15;
                const int brow = l & 7;
                const int bcol = k16 + ((l >> 3) << 3);
#pragma unroll
                for (int j = 0; j < 4; ++j)
                    ldm_x2(b[j], smem_u32(&BsRaw[(wc * 32 + j * 8 + brow) * BSTR_T + bcol]));
            } else {
                const int l = lane & 15;
#pragma unroll
                for (int j = 0; j < 4; ++j)
                    ldm_x2t(b[j], smem_u32(&BsRaw[(k16 + l) * BSTR_N + wc * 32 + j * 8]));
            }
#pragma unroll
            for (int i = 0; i < 4; ++i)
#pragma unroll
                for (int j = 0; j < 4; ++j)
                    mma16816(acc[i][j], a[i], b[j]);
        }
        __syncthreads();
    }

    // ---- epilogue ----
    const int rb = row0 + wr * 64 + (lane >> 2);
    const int cb = col0 + wc * 32 + ((lane & 3) << 1);
    if constexpr (OUT_HALF) {
        __half* C = (__half*)Cg_ + (size_t)z * strC;
#pragma unroll
        for (int i = 0; i < 4; ++i)
#pragma unroll
            for (int j = 0; j < 4; ++j) {
                int r = rb + i * 16;
                int c = cb + j * 8;
                float b0 = HAS_BIAS ? bias[c] : 0.f;
                float b1 = HAS_BIAS ? bias[c + 1] : 0.f;
                *(__half2*)(C + (size_t)r * ldc + c) =
                    __floats2half2_rn((acc[i][j][0] + b0) * scale,
                                      (acc[i][j][1] + b1) * scale);
                *(__half2*)(C + (size_t)(r + 8) * ldc + c) =
                    __floats2half2_rn((acc[i][j][2] + b0) * scale,
                                      (acc[i][j][3] + b1) * scale);
            }
    } else {
        float* C = (float*)Cg_ + (size_t)z * strC;
#pragma unroll
        for (int i = 0; i < 4; ++i)
#pragma unroll
            for (int j = 0; j < 4; ++j) {
                int r = rb + i * 16;
                int c = cb + j * 8;
                *(float2*)(C + (size_t)r * ldc + c) =
                    make_float2(acc[i][j][0], acc[i][j][1]);
                *(float2*)(C + (size_t)(r + 8) * ldc + c) =
                    make_float2(acc[i][j][2], acc[i][j][3]);
            }
    }
}

// ---------------- row softmax: S (fp32, len 2048) -> P (fp16) ---------------
__global__ void __launch_bounds__(256)
softmax_k(const float* __restrict__ S, __half* __restrict__ P)
{
    const size_t row = blockIdx.x;
    const float* s = S + row * (size_t)SEQ;
    __half* p = P + row * (size_t)SEQ;
    const int t = threadIdx.x;

    float4 v0 = *(const float4*)(s + 4 * t);
    float4 v1 = *(const float4*)(s + 1024 + 4 * t);

    float m = fmaxf(fmaxf(fmaxf(v0.x, v0.y), fmaxf(v0.z, v0.w)),
                    fmaxf(fmaxf(v1.x, v1.y), fmaxf(v1.z, v1.w)));

    __shared__ float smax[8];
    __shared__ float ssum[8];
#pragma unroll
    for (int o = 16; o; o >>= 1) m = fmaxf(m, __shfl_xor_sync(0xffffffffu, m, o));
    if ((t & 31) == 0) smax[t >> 5] = m;
    __syncthreads();
    m = smax[0];
#pragma unroll
    for (int i = 1; i < 8; ++i) m = fmaxf(m, smax[i]);

    float e[8];
    e[0] = __expf(v0.x - m); e[1] = __expf(v0.y - m);
    e[2] = __expf(v0.z - m); e[3] = __expf(v0.w - m);
    e[4] = __expf(v1.x - m); e[5] = __expf(v1.y - m);
    e[6] = __expf(v1.z - m); e[7] = __expf(v1.w - m);

    float sum = ((e[0] + e[1]) + (e[2] + e[3])) + ((e[4] + e[5]) + (e[6] + e[7]));
#pragma unroll
    for (int o = 16; o; o >>= 1) sum += __shfl_xor_sync(0xffffffffu, sum, o);
    if ((t & 31) == 0) ssum[t >> 5] = sum;
    __syncthreads();
    sum = ssum[0];
#pragma unroll
    for (int i = 1; i < 8; ++i) sum += ssum[i];

    const float inv = 1.0f / sum;

    __half2* p0 = (__half2*)(p + 4 * t);
    p0[0] = __floats2half2_rn(e[0] * inv, e[1] * inv);
    p0[1] = __floats2half2_rn(e[2] * inv, e[3] * inv);
    __half2* p1 = (__half2*)(p + 1024 + 4 * t);
    p1[0] = __floats2half2_rn(e[4] * inv, e[5] * inv);
    p1[1] = __floats2half2_rn(e[6] * inv, e[7] * inv);
}

// ---------------- launch ----------------------------------------------------
extern "C" void kernel_launch(void* const* d_in, const int* in_sizes, int n_in,
                              void* d_out, int out_size)
{
    const float* x_to   = (const float*)d_in[0];
    const float* x_from = (const float*)d_in[1];
    const float* Wq = (const float*)d_in[2];
    const float* bq = (const float*)d_in[3];
    const float* Wk = (const float*)d_in[4];
    const float* bk = (const float*)d_in[5];
    const float* Wv = (const float*)d_in[6];
    const float* bv = (const float*)d_in[7];
    float* out = (float*)d_out;

    void *pQ, *pK, *pV, *pS, *pP;
    cudaGetSymbolAddress(&pQ, g_Q);
    cudaGetSymbolAddress(&pK, g_K);
    cudaGetSymbolAddress(&pV, g_V);
    cudaGetSymbolAddress(&pS, g_S);
    cudaGetSymbolAddress(&pP, g_P);

    const float qscale = 1.0f / sqrtf((float)DM);

    // QKV projections: M = 32768, N = 768, K = 768
    dim3 gproj(DM / 128, (NB * SEQ) / 128, 1);
    gemm_k<true, false, true, true><<<gproj, 256>>>(
        x_to, Wq, bq, pQ, DM, DM, DM, DM, qscale, 0, 0, 0);
    gemm_k<true, false, true, true><<<gproj, 256>>>(
        x_from, Wk, bk, pK, DM, DM, DM, DM, 1.0f, 0, 0, 0);
    gemm_k<true, false, true, true><<<gproj, 256>>>(
        x_from, Wv, bv, pV, DM, DM, DM, DM, 1.0f, 0, 0, 0);

    // S = Q * K^T  (batched, M = N = 2048, K = 768)
    dim3 gs(SEQ / 128, SEQ / 128, NB);
    gemm_k<false, true, false, false><<<gs, 256>>>(
        pQ, pK, nullptr, pS, DM, DM, DM, SEQ, 1.0f,
        (long long)SEQ * DM, (long long)SEQ * DM, (long long)SEQ * SEQ);

    // row softmax over 2048
    softmax_k<<<NB * SEQ, 256>>>((const float*)pS, (__half*)pP);

    // O = P * V  (batched, M = 2048, N = 768, K = 2048)
    dim3 gpv(DM / 128, SEQ / 128, NB);
    gemm_k<false, false, false, false><<<gpv, 256>>>(
        pP, pV, nullptr, out, SEQ, SEQ, DM, DM, 1.0f,
        (long long)SEQ * SEQ, (long long)SEQ * DM, (long long)SEQ * DM);
}

// round 2
// speedup vs baseline: 1.4037x; 1.4037x over previous
#include <cuda_runtime.h>
#include <cuda_fp16.h>
#include <cstdint>
#include <math.h>

// Problem constants
#define NB   16
#define SEQ  2048
#define DM   768

// ---------------- scratch (device globals) ----------------------------------
__device__ __half g_xt[(long long)NB * SEQ * DM];  // x_to  fp16
__device__ __half g_xf[(long long)NB * SEQ * DM];  // x_from fp16
__device__ __half g_Wq16[DM * DM];
__device__ __half g_Wk16[DM * DM];
__device__ __half g_Wv16[DM * DM];
__device__ __half g_Q[(long long)NB * SEQ * DM];   // pre-scaled by 1/sqrt(H)
__device__ __half g_K[(long long)NB * SEQ * DM];
__device__ __half g_V[(long long)NB * SEQ * DM];
__device__ float  g_S[(long long)NB * SEQ * SEQ];
__device__ __half g_P[(long long)NB * SEQ * SEQ];

// ---------------- PTX helpers ------------------------------------------------
__device__ __forceinline__ uint32_t smem_u32(const void* p) {
    return (uint32_t)__cvta_generic_to_shared(p);
}
__device__ __forceinline__ void cp_async16(uint32_t dst, const void* src) {
    asm volatile("cp.async.cg.shared.global [%0], [%1], 16;" :: "r"(dst), "l"(src));
}
__device__ __forceinline__ void cp_commit() {
    asm volatile("cp.async.commit_group;" ::: "memory");
}
__device__ __forceinline__ void cp_wait2() {
    asm volatile("cp.async.wait_group 2;" ::: "memory");
}
__device__ __forceinline__ void ldm_x4(uint32_t* d, uint32_t a) {
    asm volatile("ldmatrix.sync.aligned.m8n8.x4.shared.b16 {%0,%1,%2,%3}, [%4];"
                 : "=r"(d[0]), "=r"(d[1]), "=r"(d[2]), "=r"(d[3]) : "r"(a));
}
__device__ __forceinline__ void ldm_x2(uint32_t* d, uint32_t a) {
    asm volatile("ldmatrix.sync.aligned.m8n8.x2.shared.b16 {%0,%1}, [%2];"
                 : "=r"(d[0]), "=r"(d[1]) : "r"(a));
}
__device__ __forceinline__ void ldm_x2t(uint32_t* d, uint32_t a) {
    asm volatile("ldmatrix.sync.aligned.m8n8.x2.trans.shared.b16 {%0,%1}, [%2];"
                 : "=r"(d[0]), "=r"(d[1]) : "r"(a));
}
__device__ __forceinline__ void mma16816(float* c, const uint32_t* a, const uint32_t* b) {
    asm volatile("mma.sync.aligned.m16n8k16.row.col.f32.f16.f16.f32 "
                 "{%0,%1,%2,%3}, {%4,%5,%6,%7}, {%8,%9}, {%0,%1,%2,%3};"
                 : "+f"(c[0]), "+f"(c[1]), "+f"(c[2]), "+f"(c[3])
                 : "r"(a[0]), "r"(a[1]), "r"(a[2]), "r"(a[3]),
                   "r"(b[0]), "r"(b[1]));
}

// ---------------- fp32 -> fp16 convert ---------------------------------------
__global__ void __launch_bounds__(256)
cvt_k(const float4* __restrict__ in, __half2* __restrict__ out, int n4)
{
    int i = blockIdx.x * 256 + threadIdx.x;
    if (i < n4) {
        float4 v = in[i];
        out[2 * i]     = __floats2half2_rn(v.x, v.y);
        out[2 * i + 1] = __floats2half2_rn(v.z, v.w);
    }
}

// ---------------- fp16 GEMM, 3-stage cp.async pipeline -----------------------
// C = A[M,K] * op(B) (+bias)*scale. TRANS_B: B is [N,K] (A*B^T) else [K,N].
// BM=BN=128, BK=32, 256 threads, 8 warps (2x4), warp tile 64x32.
template <bool TRANS_B, bool OUT_HALF, bool HAS_BIAS>
__global__ void __launch_bounds__(256)
gemm16_k(const __half* __restrict__ Ag, const __half* __restrict__ Bg,
         const float* __restrict__ bias, void* __restrict__ Cg_,
         int Kd, int lda, int ldb, int ldc, float scale,
         long long strA, long long strB, long long strC)
{
    constexpr int BM = 128, BK = 32, STAGES = 3;
    constexpr int ASTR = 40;
    constexpr int BSTR = TRANS_B ? 40 : 136;
    constexpr int A_STAGE = BM * ASTR;                    // 5120 halves
    constexpr int B_STAGE = TRANS_B ? (BM * 40) : (BK * 136);

    extern __shared__ __half sh[];
    __half* As = sh;
    __half* Bs = sh + STAGES * A_STAGE;

    const int z    = blockIdx.z;
    const int row0 = blockIdx.y * BM;
    const int col0 = blockIdx.x * 128;
    const int tid  = threadIdx.x;
    const int lane = tid & 31;
    const int warp = tid >> 5;
    const int wr   = warp >> 2;
    const int wc   = warp & 3;

    const __half* Az = Ag + (size_t)z * strA;
    const __half* Bz = Bg + (size_t)z * strB;

    // per-thread load coordinates (fixed across tiles)
    const int ar0 = tid >> 2,  ac = (tid & 3) << 3;      // A / trans-B: 2 its of (r, r+64)
    const int br0 = tid >> 4,  bc = (tid & 15) << 3;     // ntrans-B: 2 its of (r, r+16)

    auto load_tile = [&](int s, int kt) {
        __half* a = &As[s * A_STAGE];
#pragma unroll
        for (int it = 0; it < 2; ++it) {
            int r = ar0 + it * 64;
            cp_async16(smem_u32(&a[r * ASTR + ac]),
                       Az + (size_t)(row0 + r) * lda + kt + ac);
        }
        __half* b = &Bs[s * B_STAGE];
        if constexpr (TRANS_B) {
#pragma unroll
            for (int it = 0; it < 2; ++it) {
                int r = ar0 + it * 64;
                cp_async16(smem_u32(&b[r * 40 + ac]),
                           Bz + (size_t)(col0 + r) * ldb + kt + ac);
            }
        } else {
#pragma unroll
            for (int it = 0; it < 2; ++it) {
                int r = br0 + it * 16;
                cp_async16(smem_u32(&b[r * 136 + bc]),
                           Bz + (size_t)(kt + r) * ldb + col0 + bc);
            }
        }
    };

    float acc[4][4][4];
#pragma unroll
    for (int i = 0; i < 4; ++i)
#pragma unroll
        for (int j = 0; j < 4; ++j)
#pragma unroll
            for (int r = 0; r < 4; ++r) acc[i][j][r] = 0.f;

    const int ntiles = Kd / BK;

    // prologue: stages 0..1
#pragma unroll
    for (int s = 0; s < STAGES - 1; ++s) {
        load_tile(s, s * BK);
        cp_commit();
    }

    for (int i = 0; i < ntiles; ++i) {
        const int lt = i + STAGES - 1;
        if (lt < ntiles) load_tile(lt % STAGES, lt * BK);
        cp_commit();
        cp_wait2();
        __syncthreads();

        const int s = i % STAGES;
        const __half* Ab = &As[s * A_STAGE];
        const __half* Bb = &Bs[s * B_STAGE];

#pragma unroll
        for (int ks = 0; ks < 2; ++ks) {
            const int k16 = ks * 16;
            uint32_t a[4][4], b[4][2];
            const int arow = (lane & 15);
            const int acol = k16 + ((lane >> 4) << 3);
#pragma unroll
            for (int ii = 0; ii < 4; ++ii)
                ldm_x4(a[ii], smem_u32(&Ab[(wr * 64 + ii * 16 + arow) * ASTR + acol]));

            if constexpr (TRANS_B) {
                const int l = lane & 15;
                const int brow = l & 7;
                const int bcol = k16 + ((l >> 3) << 3);
#pragma unroll
                for (int j = 0; j < 4; ++j)
                    ldm_x2(b[j], smem_u32(&Bb[(wc * 32 + j * 8 + brow) * BSTR + bcol]));
            } else {
                const int l = lane & 15;
#pragma unroll
                for (int j = 0; j < 4; ++j)
                    ldm_x2t(b[j], smem_u32(&Bb[(k16 + l) * BSTR + wc * 32 + j * 8]));
            }
#pragma unroll
            for (int ii = 0; ii < 4; ++ii)
#pragma unroll
                for (int j = 0; j < 4; ++j)
                    mma16816(acc[ii][j], a[ii], b[j]);
        }
        __syncthreads();
    }

    // ---- epilogue ----
    const int rb = row0 + wr * 64 + (lane >> 2);
    const int cb = col0 + wc * 32 + ((lane & 3) << 1);
    if constexpr (OUT_HALF) {
        __half* C = (__half*)Cg_ + (size_t)z * strC;
#pragma unroll
        for (int i = 0; i < 4; ++i)
#pragma unroll
            for (int j = 0; j < 4; ++j) {
                int r = rb + i * 16;
                int c = cb + j * 8;
                float b0 = HAS_BIAS ? bias[c] : 0.f;
                float b1 = HAS_BIAS ? bias[c + 1] : 0.f;
                *(__half2*)(C + (size_t)r * ldc + c) =
                    __floats2half2_rn((acc[i][j][0] + b0) * scale,
                                      (acc[i][j][1] + b1) * scale);
                *(__half2*)(C + (size_t)(r + 8) * ldc + c) =
                    __floats2half2_rn((acc[i][j][2] + b0) * scale,
                                      (acc[i][j][3] + b1) * scale);
            }
    } else {
        float* C = (float*)Cg_ + (size_t)z * strC;
#pragma unroll
        for (int i = 0; i < 4; ++i)
#pragma unroll
            for (int j = 0; j < 4; ++j) {
                int r = rb + i * 16;
                int c = cb + j * 8;
                *(float2*)(C + (size_t)r * ldc + c) =
                    make_float2(acc[i][j][0], acc[i][j][1]);
                *(float2*)(C + (size_t)(r + 8) * ldc + c) =
                    make_float2(acc[i][j][2], acc[i][j][3]);
            }
    }
}

// ---------------- row softmax: S (fp32, len 2048) -> P (fp16) ----------------
__global__ void __launch_bounds__(256)
softmax_k(const float* __restrict__ S, __half* __restrict__ P)
{
    const size_t row = blockIdx.x;
    const float* s = S + row * (size_t)SEQ;
    __half* p = P + row * (size_t)SEQ;
    const int t = threadIdx.x;

    float4 v0 = *(const float4*)(s + 4 * t);
    float4 v1 = *(const float4*)(s + 1024 + 4 * t);

    float m = fmaxf(fmaxf(fmaxf(v0.x, v0.y), fmaxf(v0.z, v0.w)),
                    fmaxf(fmaxf(v1.x, v1.y), fmaxf(v1.z, v1.w)));

    __shared__ float smax[8];
    __shared__ float ssum[8];
#pragma unroll
    for (int o = 16; o; o >>= 1) m = fmaxf(m, __shfl_xor_sync(0xffffffffu, m, o));
    if ((t & 31) == 0) smax[t >> 5] = m;
    __syncthreads();
    m = smax[0];
#pragma unroll
    for (int i = 1; i < 8; ++i) m = fmaxf(m, smax[i]);

    float e[8];
    e[0] = __expf(v0.x - m); e[1] = __expf(v0.y - m);
    e[2] = __expf(v0.z - m); e[3] = __expf(v0.w - m);
    e[4] = __expf(v1.x - m); e[5] = __expf(v1.y - m);
    e[6] = __expf(v1.z - m); e[7] = __expf(v1.w - m);

    float sum = ((e[0] + e[1]) + (e[2] + e[3])) + ((e[4] + e[5]) + (e[6] + e[7]));
#pragma unroll
    for (int o = 16; o; o >>= 1) sum += __shfl_xor_sync(0xffffffffu, sum, o);
    if ((t & 31) == 0) ssum[t >> 5] = sum;
    __syncthreads();
    sum = ssum[0];
#pragma unroll
    for (int i = 1; i < 8; ++i) sum += ssum[i];

    const float inv = 1.0f / sum;

    __half2* p0 = (__half2*)(p + 4 * t);
    p0[0] = __floats2half2_rn(e[0] * inv, e[1] * inv);
    p0[1] = __floats2half2_rn(e[2] * inv, e[3] * inv);
    __half2* p1 = (__half2*)(p + 1024 + 4 * t);
    p1[0] = __floats2half2_rn(e[4] * inv, e[5] * inv);
    p1[1] = __floats2half2_rn(e[6] * inv, e[7] * inv);
}

// ---------------- launch ------------------------------------------------------
extern "C" void kernel_launch(void* const* d_in, const int* in_sizes, int n_in,
                              void* d_out, int out_size)
{
    const float* x_to   = (const float*)d_in[0];
    const float* x_from = (const float*)d_in[1];
    const float* Wq = (const float*)d_in[2];
    const float* bq = (const float*)d_in[3];
    const float* Wk = (const float*)d_in[4];
    const float* bk = (const float*)d_in[5];
    const float* Wv = (const float*)d_in[6];
    const float* bv = (const float*)d_in[7];
    float* out = (float*)d_out;

    void *pxt, *pxf, *pWq, *pWk, *pWv, *pQ, *pK, *pV, *pS, *pP;
    cudaGetSymbolAddress(&pxt, g_xt);
    cudaGetSymbolAddress(&pxf, g_xf);
    cudaGetSymbolAddress(&pWq, g_Wq16);
    cudaGetSymbolAddress(&pWk, g_Wk16);
    cudaGetSymbolAddress(&pWv, g_Wv16);
    cudaGetSymbolAddress(&pQ, g_Q);
    cudaGetSymbolAddress(&pK, g_K);
    cudaGetSymbolAddress(&pV, g_V);
    cudaGetSymbolAddress(&pS, g_S);
    cudaGetSymbolAddress(&pP, g_P);

    // dynamic smem sizes
    constexpr int SMEM_NT = 3 * (5120 + 32 * 136) * 2;   // 56832 B (TRANS_B=false)
    constexpr int SMEM_T  = 3 * (5120 + 5120) * 2;       // 61440 B (TRANS_B=true)
    cudaFuncSetAttribute((const void*)gemm16_k<false, true, true>,
                         cudaFuncAttributeMaxDynamicSharedMemorySize, SMEM_NT);
    cudaFuncSetAttribute((const void*)gemm16_k<true, false, false>,
                         cudaFuncAttributeMaxDynamicSharedMemorySize, SMEM_T);
    cudaFuncSetAttribute((const void*)gemm16_k<false, false, false>,
                         cudaFuncAttributeMaxDynamicSharedMemorySize, SMEM_NT);

    // ---- fp32 -> fp16 converts ----
    const int nx4 = (NB * SEQ * DM) / 4;     // 6,291,456
    const int nw4 = (DM * DM) / 4;           // 147,456
    cvt_k<<<(nx4 + 255) / 256, 256>>>((const float4*)x_to,   (__half2*)pxt, nx4);
    cvt_k<<<(nx4 + 255) / 256, 256>>>((const float4*)x_from, (__half2*)pxf, nx4);
    cvt_k<<<(nw4 + 255) / 256, 256>>>((const float4*)Wq, (__half2*)pWq, nw4);
    cvt_k<<<(nw4 + 255) / 256, 256>>>((const float4*)Wk, (__half2*)pWk, nw4);
    cvt_k<<<(nw4 + 255) / 256, 256>>>((const float4*)Wv, (__half2*)pWv, nw4);

    const float qscale = 1.0f / sqrtf((float)DM);

    // QKV projections: M = 32768, N = 768, K = 768
    dim3 gproj(DM / 128, (NB * SEQ) / 128, 1);
    gemm16_k<false, true, true><<<gproj, 256, SMEM_NT>>>(
        (const __half*)pxt, (const __half*)pWq, bq, pQ, DM, DM, DM, DM, qscale, 0, 0, 0);
    gemm16_k<false, true, true><<<gproj, 256, SMEM_NT>>>(
        (const __half*)pxf, (const __half*)pWk, bk, pK, DM, DM, DM, DM, 1.0f, 0, 0, 0);
    gemm16_k<false, true, true><<<gproj, 256, SMEM_NT>>>(
        (const __half*)pxf, (const __half*)pWv, bv, pV, DM, DM, DM, DM, 1.0f, 0, 0, 0);

    // S = Q * K^T  (batched, M = N = 2048, K = 768)
    dim3 gs(SEQ / 128, SEQ / 128, NB);
    gemm16_k<true, false, false><<<gs, 256, SMEM_T>>>(
        (const __half*)pQ, (const __half*)pK, nullptr, pS, DM, DM, DM, SEQ, 1.0f,
        (long long)SEQ * DM, (long long)SEQ * DM, (long long)SEQ * SEQ);

    // row softmax
    softmax_k<<<NB * SEQ, 256>>>((const float*)pS, (__half*)pP);

    // O = P * V  (batched, M = 2048, N = 768, K = 2048)
    dim3 gpv(DM / 128, SEQ / 128, NB);
    gemm16_k<false, false, false><<<gpv, 256, SMEM_NT>>>(
        (const __half*)pP, (const __half*)pV, nullptr, out, SEQ, SEQ, DM, DM, 1.0f,
        (long long)SEQ * SEQ, (long long)SEQ * DM, (long long)SEQ * DM);
}

// round 4
// speedup vs baseline: 2.4537x; 1.7480x over previous
#include <cuda_runtime.h>
#include <cuda_fp16.h>
#include <cstdint>
#include <math.h>

#define NB 16
#define SEQ 2048
#define DM 768

#if defined(__CUDA_ARCH_FEAT_SM103_ALL) || defined(__CUDA_ARCH_FEAT_SM100_ALL)
#define TC_PATH 1
#else
#define TC_PATH 0
#endif

// ---------------- scratch (device globals) ----------------------------------
__device__ __half g_xt[(long long)NB * SEQ * DM];
__device__ __half g_xf[(long long)NB * SEQ * DM];
__device__ __half g_WqT[DM * DM];
__device__ __half g_WkT[DM * DM];
__device__ __half g_WvT[DM * DM];
__device__ __half g_Q[(long long)NB * SEQ * DM];    // pre-scaled by 1/sqrt(H)
__device__ __half g_K[(long long)NB * SEQ * DM];
__device__ __half g_VT[(long long)NB * SEQ * DM];   // [b][768][2048]
__device__ float  g_S[(long long)NB * SEQ * SEQ];   // fp32 scores
__device__ __half g_P[(long long)NB * SEQ * SEQ];   // fp16 probs

// ---------------- common PTX helpers -----------------------------------------
__device__ __forceinline__ uint32_t smem_u32(const void* p) {
    return (uint32_t)__cvta_generic_to_shared(p);
}
__device__ __forceinline__ void cp_async16(uint32_t dst, const void* src) {
    asm volatile("cp.async.cg.shared.global [%0], [%1], 16;" :: "r"(dst), "l"(src));
}
__device__ __forceinline__ void cp_commit() {
    asm volatile("cp.async.commit_group;" ::: "memory");
}
__device__ __forceinline__ void ldm_x4(uint32_t* d, uint32_t a) {
    asm volatile("ldmatrix.sync.aligned.m8n8.x4.shared.b16 {%0,%1,%2,%3}, [%4];"
                 : "=r"(d[0]), "=r"(d[1]), "=r"(d[2]), "=r"(d[3]) : "r"(a));
}
__device__ __forceinline__ void mma16816(float* c, const uint32_t* a, const uint32_t* b) {
    asm volatile("mma.sync.aligned.m16n8k16.row.col.f32.f16.f16.f32 "
                 "{%0,%1,%2,%3}, {%4,%5,%6,%7}, {%8,%9}, {%0,%1,%2,%3};"
                 : "+f"(c[0]), "+f"(c[1]), "+f"(c[2]), "+f"(c[3])
                 : "r"(a[0]), "r"(a[1]), "r"(a[2]), "r"(a[3]),
                   "r"(b[0]), "r"(b[1]));
}

// ---------------- tcgen05 helpers (emitted only under TC_PATH) ---------------
__device__ __forceinline__ uint32_t elect_one() {
    uint32_t pred;
    asm volatile("{\n .reg .pred p;\n elect.sync _|p, 0xFFFFFFFF;\n"
                 " selp.b32 %0, 1, 0, p;\n}" : "=r"(pred));
    return pred;
}
#define MBAR_INIT(addr, cnt) \
    asm volatile("mbarrier.init.shared.b64 [%0], %1;" :: "r"(addr), "r"(cnt) : "memory")
#define MBAR_WAIT(addr, par) do {                                              \
    uint32_t _m = (addr); uint32_t _p = (par); uint32_t _done;                 \
    asm volatile("{\n .reg .pred p;\n"                                         \
        " mbarrier.try_wait.parity.acquire.cta.shared::cta.b64 p, [%1], %2;\n" \
        " selp.b32 %0, 1, 0, p;\n}"                                            \
        : "=r"(_done) : "r"(_m), "r"(_p) : "memory");                          \
    if (!_done) {                                                              \
        asm volatile("{\n .reg .pred P1;\n"                                    \
            "W_%=:\n"                                                          \
            " mbarrier.try_wait.parity.acquire.cta.shared::cta.b64 P1, [%0], %1, 0x989680;\n" \
            " @P1 bra.uni D_%=;\n bra.uni W_%=;\n"                             \
            "D_%=:\n}" :: "r"(_m), "r"(_p) : "memory");                        \
    }                                                                          \
} while (0)
#define TC_ALLOC(slot, n) \
    asm volatile("tcgen05.alloc.cta_group::1.sync.aligned.shared::cta.b32 [%0], %1;" \
                 :: "r"(slot), "r"(n) : "memory")
#define TC_DEALLOC(t, n) \
    asm volatile("tcgen05.dealloc.cta_group::1.sync.aligned.b32 %0, %1;" :: "r"(t), "r"(n))
#define TC_RELINQ() \
    asm volatile("tcgen05.relinquish_alloc_permit.cta_group::1.sync.aligned;")
#define TC_COMMIT(mbar) \
    asm volatile("tcgen05.commit.cta_group::1.mbarrier::arrive::one.shared::cluster.b64 [%0];" \
                 :: "r"(mbar) : "memory")
#define TC_FENCE_AFTER()  asm volatile("tcgen05.fence::after_thread_sync;" ::: "memory")
#define TC_FENCE_BEFORE() asm volatile("tcgen05.fence::before_thread_sync;" ::: "memory")
#define TC_WAIT_LD()      asm volatile("tcgen05.wait::ld.sync.aligned;" ::: "memory")
#define TC_LD_X32(r, addr) \
    asm volatile("tcgen05.ld.sync.aligned.32x32b.x32.b32 " \
        "{%0,%1,%2,%3,%4,%5,%6,%7,%8,%9,%10,%11,%12,%13,%14,%15," \
        "%16,%17,%18,%19,%20,%21,%22,%23,%24,%25,%26,%27,%28,%29,%30,%31}, [%32];" \
        : "=r"((r)[0]),"=r"((r)[1]),"=r"((r)[2]),"=r"((r)[3]),                  \
          "=r"((r)[4]),"=r"((r)[5]),"=r"((r)[6]),"=r"((r)[7]),                  \
          "=r"((r)[8]),"=r"((r)[9]),"=r"((r)[10]),"=r"((r)[11]),                \
          "=r"((r)[12]),"=r"((r)[13]),"=r"((r)[14]),"=r"((r)[15]),              \
          "=r"((r)[16]),"=r"((r)[17]),"=r"((r)[18]),"=r"((r)[19]),              \
          "=r"((r)[20]),"=r"((r)[21]),"=r"((r)[22]),"=r"((r)[23]),              \
          "=r"((r)[24]),"=r"((r)[25]),"=r"((r)[26]),"=r"((r)[27]),              \
          "=r"((r)[28]),"=r"((r)[29]),"=r"((r)[30]),"=r"((r)[31])               \
        : "r"(addr))

static constexpr uint64_t DESC_BASE_SW128 =
    (uint64_t(2) << 61) | (uint64_t(1) << 46) | (uint64_t(64) << 32) | (uint64_t(1) << 16);
__device__ __forceinline__ uint64_t make_desc(uint32_t addr) {
    return DESC_BASE_SW128 | ((uint64_t)(addr >> 4) & 0x3FFF);
}
__device__ __forceinline__ void mma_f16_ss(uint32_t d, uint64_t ad, uint64_t bd,
                                           uint32_t idesc, uint32_t acc) {
    asm volatile("{\n .reg .pred p;\n setp.ne.u32 p, %5, 0;\n"
        " tcgen05.mma.cta_group::1.kind::f16 [%0], %1, %2, %3, {%4,%4,%4,%4}, p;\n}"
        :: "r"(d), "l"(ad), "l"(bd), "r"(idesc), "r"(0u), "r"(acc) : "memory");
}

// ============================================================================
// Unified GEMM: C[M,N] = A[M,K] * B[N,K]^T, fp16 in, fp32 accum.
// BM=128, BN=256, BK=64, 4 stages (SW128 swizzled), 512 threads.
// TC_PATH: tcgen05 SS MMA into TMEM. Fallback: 16-warp mma.sync (warp 32x64).
// BIAS: 0 none, 1 column bias[n], 2 row bias[m].
// ============================================================================
template <int BIAS, bool OUT_HALF>
__global__ void __launch_bounds__(512, 1)
gemm_any(const __half* __restrict__ Ag, const __half* __restrict__ Bg,
         const float* __restrict__ bias, void* __restrict__ Cg,
         int Kd, int lda, int ldb, int ldc, float scale,
         long long strA, long long strB, long long strC)
{
    constexpr int BM = 128, BN = 256, BK = 64, ST = 4, PF = 3;
    constexpr int ABYTES = BM * 128;            // 16 KB
    constexpr int BBYTES = BN * 128;            // 32 KB
    constexpr int STAGE  = ABYTES + BBYTES;     // 48 KB

    extern __shared__ char dsm[];
    const uint32_t smem0 = (smem_u32(dsm) + 1023u) & ~1023u;

    const int tid  = threadIdx.x;
    const int warp = tid >> 5;
    const int lane = tid & 31;
    const int z    = blockIdx.z;
    const int row0 = blockIdx.y * BM;
    const int col0 = blockIdx.x * BN;

    const __half* Az = Ag + (size_t)z * strA;
    const __half* Bz = Bg + (size_t)z * strB;
    const int T = Kd / BK;

    auto load = [&](int s, int t) {
        const int kt = t * BK;
        const uint32_t abase = smem0 + s * STAGE;
        const uint32_t bbase = abase + ABYTES;
#pragma unroll
        for (int it = 0; it < 2; ++it) {            // A: 1024 x 16B
            int id = tid + it * 512;
            int r = id >> 3, cb = (id & 7) << 4;
            uint32_t off = (uint32_t)(r * 128 + cb);
            cp_async16(abase + (off ^ ((off >> 3) & 0x70)),
                       Az + (size_t)(row0 + r) * lda + kt + (cb >> 1));
        }
#pragma unroll
        for (int it = 0; it < 4; ++it) {            // B: 2048 x 16B
            int id = tid + it * 512;
            int r = id >> 3, cb = (id & 7) << 4;
            uint32_t off = (uint32_t)(r * 128 + cb);
            cp_async16(bbase + (off ^ ((off >> 3) & 0x70)),
                       Bz + (size_t)(col0 + r) * ldb + kt + (cb >> 1));
        }
    };

#if TC_PATH
    __shared__ __align__(8) uint64_t mbar[ST];
    __shared__ uint32_t tmem_slot;
    if (warp == 0) TC_ALLOC(smem_u32(&tmem_slot), 256);
    if (tid == 0) {
#pragma unroll
        for (int s = 0; s < ST; ++s) MBAR_INIT(smem_u32(&mbar[s]), 1);
    }
    __syncthreads();
    uint32_t tmem;
    asm volatile("ld.shared.b32 %0, [%1];" : "=r"(tmem) : "r"(smem_u32(&tmem_slot)));
    constexpr uint32_t IDESC = (1u << 4) | ((BN / 8) << 17) | ((BM / 16) << 24);
#else
    const int wr = warp >> 2;       // 0..3 : 32-row slab
    const int wc = warp & 3;        // 0..3 : 64-col slab
    float acc[2][8][4];
#pragma unroll
    for (int i = 0; i < 2; ++i)
#pragma unroll
        for (int j = 0; j < 8; ++j)
#pragma unroll
            for (int r = 0; r < 4; ++r) acc[i][j][r] = 0.f;
#endif

    // prologue: 3 tiles in flight
    load(0, 0); cp_commit();
    load(1, 1); cp_commit();
    load(2, 2); cp_commit();

    for (int i = 0; i < T; ++i) {
        const int j = i + PF;
        if (j < T) {
#if TC_PATH
            if (j >= ST) MBAR_WAIT(smem_u32(&mbar[j % ST]), ((j / ST) - 1) & 1);
#endif
            load(j % ST, j);
        }
        cp_commit();
        asm volatile("cp.async.wait_group 3;" ::: "memory");
#if TC_PATH
        asm volatile("fence.proxy.async.shared::cta;" ::: "memory");
#endif
        __syncthreads();

#if TC_PATH
        if (warp == 0 && elect_one()) {
            const int s = i % ST;
            const uint64_t ad = make_desc(smem0 + s * STAGE);
            const uint64_t bd = make_desc(smem0 + s * STAGE + ABYTES);
#pragma unroll
            for (int k = 0; k < 4; ++k)
                mma_f16_ss(tmem, ad + k * 2, bd + k * 2, IDESC,
                           (i > 0 || k > 0) ? 1u : 0u);
            TC_COMMIT(smem_u32(&mbar[s]));
        }
#else
        const uint32_t ab = smem0 + (i % ST) * STAGE;
        const uint32_t bb = ab + ABYTES;
#pragma unroll
        for (int ks = 0; ks < 4; ++ks) {
            const int kb = ks * 32;                       // byte offset of k16 group
            const int rl = lane & 15;
            const int ch = kb + ((lane >> 4) << 4);       // 16B column select
            uint32_t a[2][4], bq[4][4];
#pragma unroll
            for (int ii = 0; ii < 2; ++ii) {
                int row = wr * 32 + ii * 16 + rl;
                ldm_x4(a[ii], ab + row * 128 + (ch ^ ((row & 7) << 4)));
            }
#pragma unroll
            for (int jj = 0; jj < 4; ++jj) {
                int row = wc * 64 + jj * 16 + rl;
                ldm_x4(bq[jj], bb + row * 128 + (ch ^ ((row & 7) << 4)));
            }
#pragma unroll
            for (int ii = 0; ii < 2; ++ii)
#pragma unroll
                for (int jj = 0; jj < 4; ++jj) {
                    uint32_t b0[2] = { bq[jj][0], bq[jj][2] };
                    uint32_t b1[2] = { bq[jj][1], bq[jj][3] };
                    mma16816(acc[ii][2 * jj],     a[ii], b0);
                    mma16816(acc[ii][2 * jj + 1], a[ii], b1);
                }
        }
        __syncthreads();
#endif
    }

#if TC_PATH
    // ---- TMEM epilogue ----
    MBAR_WAIT(smem_u32(&mbar[(T - 1) % ST]), ((T - 1) / ST) & 1);
    TC_FENCE_AFTER();
    const int sub = warp & 3;                 // TMEM subpartition = warp%4
    const int cg  = warp >> 2;                // 64-col group
    const int r   = row0 + sub * 32 + lane;
    const uint32_t taddr = tmem + cg * 64;
    float rowb = 0.f;
    if (BIAS == 2) rowb = bias[r];
    uint32_t d[32];
#pragma unroll
    for (int h = 0; h < 2; ++h) {
        TC_LD_X32(d, taddr + h * 32);
        TC_WAIT_LD();
        const int cbase = col0 + cg * 64 + h * 32;
        float v[32];
#pragma unroll
        for (int jj = 0; jj < 32; ++jj) {
            float x = __uint_as_float(d[jj]);
            if (BIAS == 1) x += bias[cbase + jj];
            else if (BIAS == 2) x += rowb;
            v[jj] = x * scale;
        }
        if constexpr (OUT_HALF) {
            __half2 hb[16];
#pragma unroll
            for (int jj = 0; jj < 16; ++jj)
                hb[jj] = __floats2half2_rn(v[2 * jj], v[2 * jj + 1]);
            uint4* dst = (uint4*)((__half*)Cg + (size_t)z * strC + (size_t)r * ldc + cbase);
#pragma unroll
            for (int q = 0; q < 4; ++q) dst[q] = ((uint4*)hb)[q];
        } else {
            float4* dst = (float4*)((float*)Cg + (size_t)z * strC + (size_t)r * ldc + cbase);
#pragma unroll
            for (int q = 0; q < 8; ++q) dst[q] = ((float4*)v)[q];
        }
    }
    TC_FENCE_BEFORE();
    __syncthreads();
    if (warp == 0) {
        TC_RELINQ();
        TC_DEALLOC(tmem, 256);
    }
#else
    // ---- register epilogue ----
    const int r0 = row0 + wr * 32 + (lane >> 2);
    const int c0 = col0 + wc * 64 + ((lane & 3) << 1);
#pragma unroll
    for (int ii = 0; ii < 2; ++ii) {
        const int r = r0 + ii * 16;
        float rb0 = 0.f, rb8 = 0.f;
        if (BIAS == 2) { rb0 = bias[r]; rb8 = bias[r + 8]; }
#pragma unroll
        for (int jj = 0; jj < 8; ++jj) {
            const int c = c0 + jj * 8;
            float b0 = 0.f, b1 = 0.f;
            if (BIAS == 1) { b0 = bias[c]; b1 = bias[c + 1]; }
            float v0 = acc[ii][jj][0], v1 = acc[ii][jj][1];
            float v2 = acc[ii][jj][2], v3 = acc[ii][jj][3];
            if (BIAS == 1)      { v0 += b0; v1 += b1; v2 += b0; v3 += b1; }
            else if (BIAS == 2) { v0 += rb0; v1 += rb0; v2 += rb8; v3 += rb8; }
            v0 *= scale; v1 *= scale; v2 *= scale; v3 *= scale;
            if constexpr (OUT_HALF) {
                __half* C = (__half*)Cg + (size_t)z * strC;
                *(__half2*)(C + (size_t)r * ldc + c)       = __floats2half2_rn(v0, v1);
                *(__half2*)(C + (size_t)(r + 8) * ldc + c) = __floats2half2_rn(v2, v3);
            } else {
                float* C = (float*)Cg + (size_t)z * strC;
                *(float2*)(C + (size_t)r * ldc + c)       = make_float2(v0, v1);
                *(float2*)(C + (size_t)(r + 8) * ldc + c) = make_float2(v2, v3);
            }
        }
    }
#endif
}

// ---------------- fp32 -> fp16 convert ---------------------------------------
__global__ void __launch_bounds__(256)
cvt_k(const float4* __restrict__ in, __half2* __restrict__ out, int n4)
{
    int i = blockIdx.x * 256 + threadIdx.x;
    if (i < n4) {
        float4 v = in[i];
        out[2 * i]     = __floats2half2_rn(v.x, v.y);
        out[2 * i + 1] = __floats2half2_rn(v.z, v.w);
    }
}

// ---------------- fp32 [768,768] -> fp16 transposed --------------------------
__global__ void __launch_bounds__(256)
cvtT_k(const float* __restrict__ in, __half* __restrict__ out)
{
    __shared__ float t[32][33];
    const int bx = blockIdx.x * 32;
    const int by = blockIdx.y * 32;
    const int tx = threadIdx.x, ty = threadIdx.y;
#pragma unroll
    for (int yy = ty; yy < 32; yy += 8)
        t[yy][tx] = in[(size_t)(by + yy) * DM + bx + tx];
    __syncthreads();
#pragma unroll
    for (int yy = ty; yy < 32; yy += 8)
        out[(size_t)(bx + yy) * DM + by + tx] = __float2half(t[tx][yy]);
}

// ---------------- row softmax: S fp32 (2048) -> P fp16 -----------------------
__global__ void __launch_bounds__(256)
softmax_k(const float* __restrict__ S, __half* __restrict__ P)
{
    const size_t row = blockIdx.x;
    const float* s = S + row * (size_t)SEQ;
    __half* p = P + row * (size_t)SEQ;
    const int t = threadIdx.x;

    float4 v0 = *(const float4*)(s + 4 * t);
    float4 v1 = *(const float4*)(s + 1024 + 4 * t);

    float m = fmaxf(fmaxf(fmaxf(v0.x, v0.y), fmaxf(v0.z, v0.w)),
                    fmaxf(fmaxf(v1.x, v1.y), fmaxf(v1.z, v1.w)));

    __shared__ float smax[8], ssum[8];
#pragma unroll
    for (int o = 16; o; o >>= 1) m = fmaxf(m, __shfl_xor_sync(0xffffffffu, m, o));
    if ((t & 31) == 0) smax[t >> 5] = m;
    __syncthreads();
    m = smax[0];
#pragma unroll
    for (int i = 1; i < 8; ++i) m = fmaxf(m, smax[i]);

    float e[8];
    e[0] = __expf(v0.x - m); e[1] = __expf(v0.y - m);
    e[2] = __expf(v0.z - m); e[3] = __expf(v0.w - m);
    e[4] = __expf(v1.x - m); e[5] = __expf(v1.y - m);
    e[6] = __expf(v1.z - m); e[7] = __expf(v1.w - m);

    float sum = ((e[0] + e[1]) + (e[2] + e[3])) + ((e[4] + e[5]) + (e[6] + e[7]));
#pragma unroll
    for (int o = 16; o; o >>= 1) sum += __shfl_xor_sync(0xffffffffu, sum, o);
    if ((t & 31) == 0) ssum[t >> 5] = sum;
    __syncthreads();
    sum = ssum[0];
#pragma unroll
    for (int i = 1; i < 8; ++i) sum += ssum[i];

    const float inv = 1.0f / sum;
    __half2* p0 = (__half2*)(p + 4 * t);
    p0[0] = __floats2half2_rn(e[0] * inv, e[1] * inv);
    p0[1] = __floats2half2_rn(e[2] * inv, e[3] * inv);
    __half2* p1 = (__half2*)(p + 1024 + 4 * t);
    p1[0] = __floats2half2_rn(e[4] * inv, e[5] * inv);
    p1[1] = __floats2half2_rn(e[6] * inv, e[7] * inv);
}

// ---------------- launch ------------------------------------------------------
extern "C" void kernel_launch(void* const* d_in, const int* in_sizes, int n_in,
                              void* d_out, int out_size)
{
    const float* x_to   = (const float*)d_in[0];
    const float* x_from = (const float*)d_in[1];
    const float* Wq = (const float*)d_in[2];
    const float* bq = (const float*)d_in[3];
    const float* Wk = (const float*)d_in[4];
    const float* bk = (const float*)d_in[5];
    const float* Wv = (const float*)d_in[6];
    const float* bv = (const float*)d_in[7];
    float* out = (float*)d_out;

    void *pxt, *pxf, *pWqT, *pWkT, *pWvT, *pQ, *pK, *pVT, *pS, *pP;
    cudaGetSymbolAddress(&pxt, g_xt);
    cudaGetSymbolAddress(&pxf, g_xf);
    cudaGetSymbolAddress(&pWqT, g_WqT);
    cudaGetSymbolAddress(&pWkT, g_WkT);
    cudaGetSymbolAddress(&pWvT, g_WvT);
    cudaGetSymbolAddress(&pQ, g_Q);
    cudaGetSymbolAddress(&pK, g_K);
    cudaGetSymbolAddress(&pVT, g_VT);
    cudaGetSymbolAddress(&pS, g_S);
    cudaGetSymbolAddress(&pP, g_P);

    constexpr int SMEM = 4 * 49152 + 1024;   // 197,632 B
    cudaFuncSetAttribute((const void*)gemm_any<1, true>,
                         cudaFuncAttributeMaxDynamicSharedMemorySize, SMEM);
    cudaFuncSetAttribute((const void*)gemm_any<2, true>,
                         cudaFuncAttributeMaxDynamicSharedMemorySize, SMEM);
    cudaFuncSetAttribute((const void*)gemm_any<0, false>,
                         cudaFuncAttributeMaxDynamicSharedMemorySize, SMEM);

    // converts
    const int nx4 = (NB * SEQ * DM) / 4;
    cvt_k<<<(nx4 + 255) / 256, 256>>>((const float4*)x_to,   (__half2*)pxt, nx4);
    cvt_k<<<(nx4 + 255) / 256, 256>>>((const float4*)x_from, (__half2*)pxf, nx4);
    dim3 tb(32, 8), tg(DM / 32, DM / 32);
    cvtT_k<<<tg, tb>>>(Wq, (__half*)pWqT);
    cvtT_k<<<tg, tb>>>(Wk, (__half*)pWkT);
    cvtT_k<<<tg, tb>>>(Wv, (__half*)pWvT);

    const float qscale = 1.0f / sqrtf((float)DM);

    // Q = xt * WqT^T (+bq)*qscale ; K = xf * WkT^T (+bk)
    dim3 gq(DM / 256, (NB * SEQ) / 128, 1);
    gemm_any<1, true><<<gq, 512, SMEM>>>(
        (const __half*)pxt, (const __half*)pWqT, bq, pQ,
        DM, DM, DM, DM, qscale, 0, 0, 0);
    gemm_any<1, true><<<gq, 512, SMEM>>>(
        (const __half*)pxf, (const __half*)pWkT, bk, pK,
        DM, DM, DM, DM, 1.0f, 0, 0, 0);

    // V^T = WvT * xf^T (+bv per row), batched
    dim3 gvt(SEQ / 256, DM / 128, NB);
    gemm_any<2, true><<<gvt, 512, SMEM>>>(
        (const __half*)pWvT, (const __half*)pxf, bv, pVT,
        DM, DM, DM, SEQ, 1.0f, 0, (long long)SEQ * DM, (long long)DM * SEQ);

    // S = Q * K^T (fp32 out), batched
    dim3 gs(SEQ / 256, SEQ / 128, NB);
    gemm_any<0, false><<<gs, 512, SMEM>>>(
        (const __half*)pQ, (const __half*)pK, nullptr, pS,
        DM, DM, DM, SEQ, 1.0f,
        (long long)SEQ * DM, (long long)SEQ * DM, (long long)SEQ * SEQ);

    // softmax
    softmax_k<<<NB * SEQ, 256>>>((const float*)pS, (__half*)pP);

    // O = P * (V^T)^T (fp32 out), batched
    dim3 go(DM / 256, SEQ / 128, NB);
    gemm_any<0, false><<<go, 512, SMEM>>>(
        (const __half*)pP, (const __half*)pVT, nullptr, out,
        SEQ, SEQ, SEQ, DM, 1.0f,
        (long long)SEQ * SEQ, (long long)DM * SEQ, (long long)SEQ * DM);
}

// round 5
// speedup vs baseline: 2.9934x; 1.2200x over previous
#include <cuda_runtime.h>
#include <cuda_fp16.h>
#include <cstdint>
#include <math.h>

#define NB 16
#define SEQ 2048
#define DM 768

#if defined(__CUDA_ARCH_FEAT_SM103_ALL) || defined(__CUDA_ARCH_FEAT_SM100_ALL)
#define TC_PATH 1
#else
#define TC_PATH 0
#endif

// ---------------- scratch (device globals) ----------------------------------
__device__ __half g_xt[(long long)NB * SEQ * DM];
__device__ __half g_xf[(long long)NB * SEQ * DM];
__device__ __half g_WqT[DM * DM];
__device__ __half g_WkT[DM * DM];
__device__ __half g_WvT[DM * DM];
__device__ __half g_Q[(long long)NB * SEQ * DM];    // pre-scaled by 1/sqrt(H)
__device__ __half g_K[(long long)NB * SEQ * DM];
__device__ __half g_VT[(long long)NB * SEQ * DM];   // [b][768][2048]
__device__ __half g_E[(long long)NB * SEQ * SEQ];   // exp(scores), fp16
__device__ float  g_inv[(long long)NB * SEQ];       // 1 / rowsum(E)

// ---------------- common PTX helpers -----------------------------------------
__device__ __forceinline__ uint32_t smem_u32(const void* p) {
    return (uint32_t)__cvta_generic_to_shared(p);
}
__device__ __forceinline__ void cp_async16(uint32_t dst, const void* src) {
    asm volatile("cp.async.cg.shared.global [%0], [%1], 16;" :: "r"(dst), "l"(src));
}
__device__ __forceinline__ void cp_commit() {
    asm volatile("cp.async.commit_group;" ::: "memory");
}
__device__ __forceinline__ void ldm_x4(uint32_t* d, uint32_t a) {
    asm volatile("ldmatrix.sync.aligned.m8n8.x4.shared.b16 {%0,%1,%2,%3}, [%4];"
                 : "=r"(d[0]), "=r"(d[1]), "=r"(d[2]), "=r"(d[3]) : "r"(a));
}
__device__ __forceinline__ void mma16816(float* c, const uint32_t* a, const uint32_t* b) {
    asm volatile("mma.sync.aligned.m16n8k16.row.col.f32.f16.f16.f32 "
                 "{%0,%1,%2,%3}, {%4,%5,%6,%7}, {%8,%9}, {%0,%1,%2,%3};"
                 : "+f"(c[0]), "+f"(c[1]), "+f"(c[2]), "+f"(c[3])
                 : "r"(a[0]), "r"(a[1]), "r"(a[2]), "r"(a[3]),
                   "r"(b[0]), "r"(b[1]));
}

// ---------------- tcgen05 helpers (dead code under compute_103) --------------
__device__ __forceinline__ uint32_t elect_one() {
    uint32_t pred;
    asm volatile("{\n .reg .pred p;\n elect.sync _|p, 0xFFFFFFFF;\n"
                 " selp.b32 %0, 1, 0, p;\n}" : "=r"(pred));
    return pred;
}
#define MBAR_INIT(addr, cnt) \
    asm volatile("mbarrier.init.shared.b64 [%0], %1;" :: "r"(addr), "r"(cnt) : "memory")
#define MBAR_WAIT(addr, par) do {                                              \
    uint32_t _m = (addr); uint32_t _p = (par); uint32_t _done;                 \
    asm volatile("{\n .reg .pred p;\n"                                         \
        " mbarrier.try_wait.parity.acquire.cta.shared::cta.b64 p, [%1], %2;\n" \
        " selp.b32 %0, 1, 0, p;\n}"                                            \
        : "=r"(_done) : "r"(_m), "r"(_p) : "memory");                          \
    if (!_done) {                                                              \
        asm volatile("{\n .reg .pred P1;\n"                                    \
            "W_%=:\n"                                                          \
            " mbarrier.try_wait.parity.acquire.cta.shared::cta.b64 P1, [%0], %1, 0x989680;\n" \
            " @P1 bra.uni D_%=;\n bra.uni W_%=;\n"                             \
            "D_%=:\n}" :: "r"(_m), "r"(_p) : "memory");                        \
    }                                                                          \
} while (0)
#if TC_PATH
#define TC_ALLOC(slot, n) \
    asm volatile("tcgen05.alloc.cta_group::1.sync.aligned.shared::cta.b32 [%0], %1;" \
                 :: "r"(slot), "r"(n) : "memory")
#define TC_DEALLOC(t, n) \
    asm volatile("tcgen05.dealloc.cta_group::1.sync.aligned.b32 %0, %1;" :: "r"(t), "r"(n))
#define TC_RELINQ() \
    asm volatile("tcgen05.relinquish_alloc_permit.cta_group::1.sync.aligned;")
#define TC_COMMIT(mbar) \
    asm volatile("tcgen05.commit.cta_group::1.mbarrier::arrive::one.shared::cluster.b64 [%0];" \
                 :: "r"(mbar) : "memory")
#define TC_FENCE_AFTER()  asm volatile("tcgen05.fence::after_thread_sync;" ::: "memory")
#define TC_FENCE_BEFORE() asm volatile("tcgen05.fence::before_thread_sync;" ::: "memory")
#define TC_WAIT_LD()      asm volatile("tcgen05.wait::ld.sync.aligned;" ::: "memory")
#define TC_LD_X32(r, addr) \
    asm volatile("tcgen05.ld.sync.aligned.32x32b.x32.b32 " \
        "{%0,%1,%2,%3,%4,%5,%6,%7,%8,%9,%10,%11,%12,%13,%14,%15," \
        "%16,%17,%18,%19,%20,%21,%22,%23,%24,%25,%26,%27,%28,%29,%30,%31}, [%32];" \
        : "=r"((r)[0]),"=r"((r)[1]),"=r"((r)[2]),"=r"((r)[3]),                  \
          "=r"((r)[4]),"=r"((r)[5]),"=r"((r)[6]),"=r"((r)[7]),                  \
          "=r"((r)[8]),"=r"((r)[9]),"=r"((r)[10]),"=r"((r)[11]),                \
          "=r"((r)[12]),"=r"((r)[13]),"=r"((r)[14]),"=r"((r)[15]),              \
          "=r"((r)[16]),"=r"((r)[17]),"=r"((r)[18]),"=r"((r)[19]),              \
          "=r"((r)[20]),"=r"((r)[21]),"=r"((r)[22]),"=r"((r)[23]),              \
          "=r"((r)[24]),"=r"((r)[25]),"=r"((r)[26]),"=r"((r)[27]),              \
          "=r"((r)[28]),"=r"((r)[29]),"=r"((r)[30]),"=r"((r)[31])               \
        : "r"(addr))

static constexpr uint64_t DESC_BASE_SW128 =
    (uint64_t(2) << 61) | (uint64_t(1) << 46) | (uint64_t(64) << 32) | (uint64_t(1) << 16);
__device__ __forceinline__ uint64_t make_desc(uint32_t addr) {
    return DESC_BASE_SW128 | ((uint64_t)(addr >> 4) & 0x3FFF);
}
__device__ __forceinline__ void mma_f16_ss(uint32_t d, uint64_t ad, uint64_t bd,
                                           uint32_t idesc, uint32_t acc) {
    asm volatile("{\n .reg .pred p;\n setp.ne.u32 p, %5, 0;\n"
        " tcgen05.mma.cta_group::1.kind::f16 [%0], %1, %2, %3, {%4,%4,%4,%4}, p;\n}"
        :: "r"(d), "l"(ad), "l"(bd), "r"(idesc), "r"(0u), "r"(acc) : "memory");
}
#endif

// ============================================================================
// Unified GEMM: C[M,N] = A[M,K] * B[N,K]^T, fp16 in, fp32 accum.
// BM=128, BN=256, BK=64, 4 stages SW128, 512 threads, PF=2, ONE sync/tile.
// MODE: 0 plain(*scale)  1 +bias[n], *scale  2 +bias[m]
//       3 exp(acc) (OUT_HALF)                4 acc * rowscale[m] (array)
// ============================================================================
template <int MODE, bool OUT_HALF>
__global__ void __launch_bounds__(512, 1)
gemm_any(const __half* __restrict__ Ag, const __half* __restrict__ Bg,
         const float* __restrict__ bias, void* __restrict__ Cg,
         int Kd, int lda, int ldb, int ldc, float scale,
         long long strA, long long strB, long long strC, long long strBias)
{
    constexpr int BM = 128, BN = 256, BK = 64, ST = 4, PF = 2;
    constexpr int ABYTES = BM * 128;            // 16 KB
    constexpr int BBYTES = BN * 128;            // 32 KB
    constexpr int STAGE  = ABYTES + BBYTES;     // 48 KB

    extern __shared__ char dsm[];
    const uint32_t smem0 = (smem_u32(dsm) + 1023u) & ~1023u;

    const int tid  = threadIdx.x;
    const int warp = tid >> 5;
    const int lane = tid & 31;
    const int z    = blockIdx.z;
    const int row0 = blockIdx.y * BM;
    const int col0 = blockIdx.x * BN;

    const __half* Az = Ag + (size_t)z * strA;
    const __half* Bz = Bg + (size_t)z * strB;
    const float* bz = bias ? (bias + (size_t)z * strBias) : bias;
    const int T = Kd / BK;

    auto load = [&](int s, int t) {
        const int kt = t * BK;
        const uint32_t abase = smem0 + s * STAGE;
        const uint32_t bbase = abase + ABYTES;
#pragma unroll
        for (int it = 0; it < 2; ++it) {            // A: 1024 x 16B
            int id = tid + it * 512;
            int r = id >> 3, cb = (id & 7) << 4;
            uint32_t off = (uint32_t)(r * 128 + cb);
            cp_async16(abase + (off ^ ((off >> 3) & 0x70)),
                       Az + (size_t)(row0 + r) * lda + kt + (cb >> 1));
        }
#pragma unroll
        for (int it = 0; it < 4; ++it) {            // B: 2048 x 16B
            int id = tid + it * 512;
            int r = id >> 3, cb = (id & 7) << 4;
            uint32_t off = (uint32_t)(r * 128 + cb);
            cp_async16(bbase + (off ^ ((off >> 3) & 0x70)),
                       Bz + (size_t)(col0 + r) * ldb + kt + (cb >> 1));
        }
    };

#if TC_PATH
    __shared__ __align__(8) uint64_t mbar[ST];
    __shared__ uint32_t tmem_slot;
    if (warp == 0) TC_ALLOC(smem_u32(&tmem_slot), 256);
    if (tid == 0) {
#pragma unroll
        for (int s = 0; s < ST; ++s) MBAR_INIT(smem_u32(&mbar[s]), 1);
    }
    __syncthreads();
    uint32_t tmem;
    asm volatile("ld.shared.b32 %0, [%1];" : "=r"(tmem) : "r"(smem_u32(&tmem_slot)));
    constexpr uint32_t IDESC = (1u << 4) | ((BN / 8) << 17) | ((BM / 16) << 24);
#else
    const int wr = warp >> 2;       // 0..3 : 32-row slab
    const int wc = warp & 3;        // 0..3 : 64-col slab
    float acc[2][8][4];
#pragma unroll
    for (int i = 0; i < 2; ++i)
#pragma unroll
        for (int j = 0; j < 8; ++j)
#pragma unroll
            for (int r = 0; r < 4; ++r) acc[i][j][r] = 0.f;
#endif

    // prologue: 2 tiles in flight
    load(0, 0); cp_commit();
    load(1, 1); cp_commit();

    for (int i = 0; i < T; ++i) {
        const int j = i + PF;
        if (j < T) {
#if TC_PATH
            if (j >= ST) MBAR_WAIT(smem_u32(&mbar[j % ST]), ((j / ST) - 1) & 1);
#endif
            load(j % ST, j);
        }
        cp_commit();
        asm volatile("cp.async.wait_group 2;" ::: "memory");
#if TC_PATH
        asm volatile("fence.proxy.async.shared::cta;" ::: "memory");
#endif
        __syncthreads();

#if TC_PATH
        if (warp == 0 && elect_one()) {
            const int s = i % ST;
            const uint64_t ad = make_desc(smem0 + s * STAGE);
            const uint64_t bd = make_desc(smem0 + s * STAGE + ABYTES);
#pragma unroll
            for (int k = 0; k < 4; ++k)
                mma_f16_ss(tmem, ad + k * 2, bd + k * 2, IDESC,
                           (i > 0 || k > 0) ? 1u : 0u);
            TC_COMMIT(smem_u32(&mbar[i % ST]));
        }
        __syncthreads();   // TC path keeps trailing sync (mbar pacing differs)
#else
        const uint32_t ab = smem0 + (i % ST) * STAGE;
        const uint32_t bb = ab + ABYTES;
#pragma unroll
        for (int ks = 0; ks < 4; ++ks) {
            const int kb = ks * 32;
            const int rl = lane & 15;
            const int ch = kb + ((lane >> 4) << 4);
            uint32_t a[2][4], bq[4][4];
#pragma unroll
            for (int ii = 0; ii < 2; ++ii) {
                int row = wr * 32 + ii * 16 + rl;
                ldm_x4(a[ii], ab + row * 128 + (ch ^ ((row & 7) << 4)));
            }
#pragma unroll
            for (int jj = 0; jj < 4; ++jj) {
                int row = wc * 64 + jj * 16 + rl;
                ldm_x4(bq[jj], bb + row * 128 + (ch ^ ((row & 7) << 4)));
            }
#pragma unroll
            for (int ii = 0; ii < 2; ++ii)
#pragma unroll
                for (int jj = 0; jj < 4; ++jj) {
                    uint32_t b0[2] = { bq[jj][0], bq[jj][2] };
                    uint32_t b1[2] = { bq[jj][1], bq[jj][3] };
                    mma16816(acc[ii][2 * jj],     a[ii], b0);
                    mma16816(acc[ii][2 * jj + 1], a[ii], b1);
                }
        }
        // no trailing sync: stage i%4 is next written at iter i+2, after sync(i+1)
#endif
    }

#if TC_PATH
    MBAR_WAIT(smem_u32(&mbar[(T - 1) % ST]), ((T - 1) / ST) & 1);
    TC_FENCE_AFTER();
    const int sub = warp & 3;
    const int cg  = warp >> 2;
    const int r   = row0 + sub * 32 + lane;
    const uint32_t taddr = tmem + cg * 64;
    float rowf = 0.f;
    if (MODE == 2) rowf = bz[r];
    if (MODE == 4) rowf = bz[r];
    uint32_t d[32];
#pragma unroll
    for (int h = 0; h < 2; ++h) {
        TC_LD_X32(d, taddr + h * 32);
        TC_WAIT_LD();
        const int cbase = col0 + cg * 64 + h * 32;
        float v[32];
#pragma unroll
        for (int jj = 0; jj < 32; ++jj) {
            float x = __uint_as_float(d[jj]);
            if (MODE == 1)      v[jj] = (x + bz[cbase + jj]) * scale;
            else if (MODE == 2) v[jj] = x + rowf;
            else if (MODE == 3) v[jj] = __expf(x);
            else if (MODE == 4) v[jj] = x * rowf;
            else                v[jj] = x * scale;
        }
        if constexpr (OUT_HALF) {
            __half2 hb[16];
#pragma unroll
            for (int jj = 0; jj < 16; ++jj)
                hb[jj] = __floats2half2_rn(v[2 * jj], v[2 * jj + 1]);
            uint4* dst = (uint4*)((__half*)Cg + (size_t)z * strC + (size_t)r * ldc + cbase);
#pragma unroll
            for (int q = 0; q < 4; ++q) dst[q] = ((uint4*)hb)[q];
        } else {
            float4* dst = (float4*)((float*)Cg + (size_t)z * strC + (size_t)r * ldc + cbase);
#pragma unroll
            for (int q = 0; q < 8; ++q) dst[q] = ((float4*)v)[q];
        }
    }
    TC_FENCE_BEFORE();
    __syncthreads();
    if (warp == 0) { TC_RELINQ(); TC_DEALLOC(tmem, 256); }
#else
    const int r0 = row0 + wr * 32 + (lane >> 2);
    const int c0 = col0 + wc * 64 + ((lane & 3) << 1);
#pragma unroll
    for (int ii = 0; ii < 2; ++ii) {
        const int r = r0 + ii * 16;
        float rf0 = 0.f, rf8 = 0.f;
        if (MODE == 2 || MODE == 4) { rf0 = bz[r]; rf8 = bz[r + 8]; }
#pragma unroll
        for (int jj = 0; jj < 8; ++jj) {
            const int c = c0 + jj * 8;
            float v0 = acc[ii][jj][0], v1 = acc[ii][jj][1];
            float v2 = acc[ii][jj][2], v3 = acc[ii][jj][3];
            if (MODE == 1) {
                float b0 = bz[c], b1 = bz[c + 1];
                v0 = (v0 + b0) * scale; v1 = (v1 + b1) * scale;
                v2 = (v2 + b0) * scale; v3 = (v3 + b1) * scale;
            } else if (MODE == 2) {
                v0 += rf0; v1 += rf0; v2 += rf8; v3 += rf8;
            } else if (MODE == 3) {
                v0 = __expf(v0); v1 = __expf(v1);
                v2 = __expf(v2); v3 = __expf(v3);
            } else if (MODE == 4) {
                v0 *= rf0; v1 *= rf0; v2 *= rf8; v3 *= rf8;
            } else {
                v0 *= scale; v1 *= scale; v2 *= scale; v3 *= scale;
            }
            if constexpr (OUT_HALF) {
                __half* C = (__half*)Cg + (size_t)z * strC;
                *(__half2*)(C + (size_t)r * ldc + c)       = __floats2half2_rn(v0, v1);
                *(__half2*)(C + (size_t)(r + 8) * ldc + c) = __floats2half2_rn(v2, v3);
            } else {
                float* C = (float*)Cg + (size_t)z * strC;
                *(float2*)(C + (size_t)r * ldc + c)       = make_float2(v0, v1);
                *(float2*)(C + (size_t)(r + 8) * ldc + c) = make_float2(v2, v3);
            }
        }
    }
#endif
}

// ---------------- fp32 -> fp16 convert ---------------------------------------
__global__ void __launch_bounds__(256)
cvt_k(const float4* __restrict__ in, __half2* __restrict__ out, int n4)
{
    int i = blockIdx.x * 256 + threadIdx.x;
    if (i < n4) {
        float4 v = in[i];
        out[2 * i]     = __floats2half2_rn(v.x, v.y);
        out[2 * i + 1] = __floats2half2_rn(v.z, v.w);
    }
}

// ---------------- fp32 [768,768] -> fp16 transposed --------------------------
__global__ void __launch_bounds__(256)
cvtT_k(const float* __restrict__ in, __half* __restrict__ out)
{
    __shared__ float t[32][33];
    const int bx = blockIdx.x * 32;
    const int by = blockIdx.y * 32;
    const int tx = threadIdx.x, ty = threadIdx.y;
#pragma unroll
    for (int yy = ty; yy < 32; yy += 8)
        t[yy][tx] = in[(size_t)(by + yy) * DM + bx + tx];
    __syncthreads();
#pragma unroll
    for (int yy = ty; yy < 32; yy += 8)
        out[(size_t)(bx + yy) * DM + by + tx] = __float2half(t[tx][yy]);
}

// ---------------- rowsum: inv[row] = 1 / sum(E[row, 0:2048]) -----------------
__global__ void __launch_bounds__(256)
rowsum_k(const __half* __restrict__ E, float* __restrict__ inv)
{
    const size_t row = blockIdx.x;
    const __half* e = E + row * (size_t)SEQ;
    const int t = threadIdx.x;

    uint4 raw = *(const uint4*)(e + 8 * t);
    __half2 h[4] = {*(__half2*)&raw.x, *(__half2*)&raw.y,
                    *(__half2*)&raw.z, *(__half2*)&raw.w};
    float sum = 0.f;
#pragma unroll
    for (int i = 0; i < 4; ++i) {
        float2 f = __half22float2(h[i]);
        sum += f.x + f.y;
    }
    __shared__ float ssum[8];
#pragma unroll
    for (int o = 16; o; o >>= 1) sum += __shfl_xor_sync(0xffffffffu, sum, o);
    if ((t & 31) == 0) ssum[t >> 5] = sum;
    __syncthreads();
    if (t == 0) {
        float s = ssum[0];
#pragma unroll
        for (int i = 1; i < 8; ++i) s += ssum[i];
        inv[row] = 1.0f / s;
    }
}

// ---------------- launch ------------------------------------------------------
extern "C" void kernel_launch(void* const* d_in, const int* in_sizes, int n_in,
                              void* d_out, int out_size)
{
    const float* x_to   = (const float*)d_in[0];
    const float* x_from = (const float*)d_in[1];
    const float* Wq = (const float*)d_in[2];
    const float* bq = (const float*)d_in[3];
    const float* Wk = (const float*)d_in[4];
    const float* bk = (const float*)d_in[5];
    const float* Wv = (const float*)d_in[6];
    const float* bv = (const float*)d_in[7];
    float* out = (float*)d_out;

    void *pxt, *pxf, *pWqT, *pWkT, *pWvT, *pQ, *pK, *pVT, *pE, *pInv;
    cudaGetSymbolAddress(&pxt, g_xt);
    cudaGetSymbolAddress(&pxf, g_xf);
    cudaGetSymbolAddress(&pWqT, g_WqT);
    cudaGetSymbolAddress(&pWkT, g_WkT);
    cudaGetSymbolAddress(&pWvT, g_WvT);
    cudaGetSymbolAddress(&pQ, g_Q);
    cudaGetSymbolAddress(&pK, g_K);
    cudaGetSymbolAddress(&pVT, g_VT);
    cudaGetSymbolAddress(&pE, g_E);
    cudaGetSymbolAddress(&pInv, g_inv);

    constexpr int SMEM = 4 * 49152 + 1024;   // 197,632 B
    cudaFuncSetAttribute((const void*)gemm_any<1, true>,
                         cudaFuncAttributeMaxDynamicSharedMemorySize, SMEM);
    cudaFuncSetAttribute((const void*)gemm_any<2, true>,
                         cudaFuncAttributeMaxDynamicSharedMemorySize, SMEM);
    cudaFuncSetAttribute((const void*)gemm_any<3, true>,
                         cudaFuncAttributeMaxDynamicSharedMemorySize, SMEM);
    cudaFuncSetAttribute((const void*)gemm_any<4, false>,
                         cudaFuncAttributeMaxDynamicSharedMemorySize, SMEM);

    // converts
    const int nx4 = (NB * SEQ * DM) / 4;
    cvt_k<<<(nx4 + 255) / 256, 256>>>((const float4*)x_to,   (__half2*)pxt, nx4);
    cvt_k<<<(nx4 + 255) / 256, 256>>>((const float4*)x_from, (__half2*)pxf, nx4);
    dim3 tb(32, 8), tg(DM / 32, DM / 32);
    cvtT_k<<<tg, tb>>>(Wq, (__half*)pWqT);
    cvtT_k<<<tg, tb>>>(Wk, (__half*)pWkT);
    cvtT_k<<<tg, tb>>>(Wv, (__half*)pWvT);

    const float qscale = 1.0f / sqrtf((float)DM);

    // Q = xt * WqT^T (+bq)*qscale ; K = xf * WkT^T (+bk)
    dim3 gq(DM / 256, (NB * SEQ) / 128, 1);
    gemm_any<1, true><<<gq, 512, SMEM>>>(
        (const __half*)pxt, (const __half*)pWqT, bq, pQ,
        DM, DM, DM, DM, qscale, 0, 0, 0, 0);
    gemm_any<1, true><<<gq, 512, SMEM>>>(
        (const __half*)pxf, (const __half*)pWkT, bk, pK,
        DM, DM, DM, DM, 1.0f, 0, 0, 0, 0);

    // V^T = WvT * xf^T (+bv per row), batched
    dim3 gvt(SEQ / 256, DM / 128, NB);
    gemm_any<2, true><<<gvt, 512, SMEM>>>(
        (const __half*)pWvT, (const __half*)pxf, bv, pVT,
        DM, DM, DM, SEQ, 1.0f, 0, (long long)SEQ * DM, (long long)DM * SEQ, 0);

    // E = exp(Q * K^T), batched, fp16 out
    dim3 gs(SEQ / 256, SEQ / 128, NB);
    gemm_any<3, true><<<gs, 512, SMEM>>>(
        (const __half*)pQ, (const __half*)pK, nullptr, pE,
        DM, DM, DM, SEQ, 1.0f,
        (long long)SEQ * DM, (long long)SEQ * DM, (long long)SEQ * SEQ, 0);

    // inv[row] = 1 / rowsum(E)
    rowsum_k<<<NB * SEQ, 256>>>((const __half*)pE, (float*)pInv);

    // out = (E * V) * inv[row], batched, fp32 out
    dim3 go(DM / 256, SEQ / 128, NB);
    gemm_any<4, false><<<go, 512, SMEM>>>(
        (const __half*)pE, (const __half*)pVT, (const float*)pInv, out,
        SEQ, SEQ, SEQ, DM, 1.0f,
        (long long)SEQ * SEQ, (long long)DM * SEQ, (long long)SEQ * DM, SEQ);
}